// round 16
// baseline (speedup 1.0000x reference)
#include <cuda_runtime.h>
#include <cuda_bf16.h>
#include <cuda_fp8.h>
#include <math.h>
#include <stdint.h>

// ---------------- problem constants ----------------
#define NROWS 4096
#define DDIM  768
#define DINNER 256
#define MCTX  32768
#define H1DIM 512
#define H2DIM 256

typedef __nv_bfloat16 bf16;

// ---------------- scratch (device globals; no allocation allowed) ----------------
__device__ uint8_t g_S[(size_t)NROWS * MCTX];      // exp(logits)/16 as e4m3
__device__ uint8_t g_Vt8[(size_t)DDIM * MCTX];     // ctx_v^T as e4m3
__device__ bf16 g_Kc[(size_t)MCTX * DINNER];
__device__ bf16 g_Xh[(size_t)NROWS * DDIM];
__device__ bf16 g_Xl[(size_t)NROWS * DDIM];
__device__ bf16 g_Qb[(size_t)NROWS * DINNER];
__device__ bf16 g_X2h[(size_t)NROWS * DDIM];
__device__ bf16 g_X2th[(size_t)DDIM * NROWS];
__device__ bf16 g_QKm[(size_t)NROWS * 1536];       // Qm | Km concat
__device__ bf16 g_A2h[(size_t)NROWS * NROWS];
__device__ bf16 g_Th[(size_t)NROWS * DDIM];
__device__ bf16 g_Hh[(size_t)NROWS * DDIM];
__device__ bf16 g_Hl[(size_t)NROWS * DDIM];
__device__ bf16 g_H1h[(size_t)NROWS * H1DIM];
__device__ bf16 g_H1l[(size_t)NROWS * H1DIM];
// pre-transposed weights
__device__ bf16 g_Wqh_h[(size_t)DINNER * DDIM];
__device__ bf16 g_Wqh_l[(size_t)DINNER * DDIM];
__device__ bf16 g_Wqkm[(size_t)1536 * DDIM];
__device__ bf16 g_Wg_h[(size_t)DDIM * DDIM];
__device__ bf16 g_W1_h[(size_t)H1DIM * DDIM];
__device__ bf16 g_W1_l[(size_t)H1DIM * DDIM];
__device__ bf16 g_W2_h[(size_t)H2DIM * H1DIM];
__device__ bf16 g_W2_l[(size_t)H2DIM * H1DIM];
// fp32
__device__ float g_X2[(size_t)NROWS * DDIM];
__device__ float g_H2[(size_t)NROWS * H2DIM];
__device__ float g_invS[NROWS];
__device__ float g_invA[NROWS];
__device__ float g_part[(size_t)8 * NROWS * DDIM];
__device__ float g_psum[(size_t)512 * NROWS];

// ---------------- helpers ----------------
__device__ __forceinline__ uint32_t smem_u32(const void* p) {
    uint32_t a;
    asm("{ .reg .u64 t; cvta.to.shared.u64 t, %1; cvt.u32.u64 %0, t; }" : "=r"(a) : "l"(p));
    return a;
}
#define SWZ(off) ((off) ^ (((off) >> 3) & 0x70))

__device__ __forceinline__ uint32_t packbf(float x0, float x1) {
    uint32_t r;
    asm("cvt.rn.bf16x2.f32 %0, %1, %2;" : "=r"(r) : "f"(x1), "f"(x0));
    return r;
}
__device__ __forceinline__ uint16_t packf8(float x0, float x1) {
    uint16_t r;  // byte0 = x0, byte1 = x1
    asm("cvt.rn.satfinite.e4m3x2.f32 %0, %1, %2;" : "=h"(r) : "f"(x1), "f"(x0));
    return r;
}
__device__ __forceinline__ void splitbf(float x, float& h, float& l) {
    h = __bfloat162float(__float2bfloat16(x));
    l = x - h;
}
__device__ __forceinline__ float gelu_exact(float x) {
    return 0.5f * x * (1.0f + erff(x * 0.70710678118654752f));
}
__device__ __forceinline__ float softplus_stable(float x) {
    return (x > 20.0f) ? x : log1pf(expf(x));
}
__device__ __forceinline__ float exp_fast(float x) {
    x = fminf(fmaxf(x, -87.0f), 87.0f);
    float y = x * 1.4426950408889634f;
    float n = rintf(y);
    float f = y - n;
    float p =       1.33335581e-3f;
    p = fmaf(p, f,  9.61812911e-3f);
    p = fmaf(p, f,  5.55041087e-2f);
    p = fmaf(p, f,  2.40226507e-1f);
    p = fmaf(p, f,  6.93147182e-1f);
    p = fmaf(p, f,  1.0f);
    return __int_as_float(__float_as_int(p) + ((int)n << 23));
}

__device__ __forceinline__ void cpa16(uint32_t dst, const void* src) {
    asm volatile("cp.async.cg.shared.global [%0], [%1], 16;" :: "r"(dst), "l"(src));
}
__device__ __forceinline__ void cpa_commit() {
    asm volatile("cp.async.commit_group;" ::: "memory");
}
template<int N>
__device__ __forceinline__ void cpa_wait() {
    asm volatile("cp.async.wait_group %0;" :: "n"(N) : "memory");
}

__device__ __forceinline__ void ldsm4(uint32_t* r, uint32_t addr) {
    asm volatile("ldmatrix.sync.aligned.m8n8.x4.shared.b16 {%0,%1,%2,%3}, [%4];"
        : "=r"(r[0]), "=r"(r[1]), "=r"(r[2]), "=r"(r[3]) : "r"(addr));
}
__device__ __forceinline__ void mma16(float* d, const uint32_t* a, uint32_t b0, uint32_t b1) {
    asm volatile("mma.sync.aligned.m16n8k16.row.col.f32.bf16.bf16.f32 "
        "{%0,%1,%2,%3}, {%4,%5,%6,%7}, {%8,%9}, {%0,%1,%2,%3};"
        : "+f"(d[0]), "+f"(d[1]), "+f"(d[2]), "+f"(d[3])
        : "r"(a[0]), "r"(a[1]), "r"(a[2]), "r"(a[3]), "r"(b0), "r"(b1));
}
__device__ __forceinline__ void mma32f8(float* d, const uint32_t* a, uint32_t b0, uint32_t b1) {
    asm volatile("mma.sync.aligned.m16n8k32.row.col.f32.e4m3.e4m3.f32 "
        "{%0,%1,%2,%3}, {%4,%5,%6,%7}, {%8,%9}, {%0,%1,%2,%3};"
        : "+f"(d[0]), "+f"(d[1]), "+f"(d[2]), "+f"(d[3])
        : "r"(a[0]), "r"(a[1]), "r"(a[2]), "r"(a[3]), "r"(b0), "r"(b1));
}

// ---------------- unified GEMM (bf16 or e4m3 operands, K-major) ----------------
// C[4096,N] = epi(A @ B^T). ET=bf16: m16n8k16, 64-elem K chunks.
// ET=uint8 (e4m3): m16n8k32, 128-elem K chunks — SAME 128B-row smem layout,
// SAME swizzle/ldsm addressing (fp8-pair == b16 unit), only the mma differs.
// Two-sync 3-stage cp.async pipeline (proven; do not reorder).
#define EPI_NONE 0
#define EPI_EXP 1
#define EPI_BG 2
#define EPI_BGR 3

#define NST 3

template<int PASSES, int EPI, bool OSPLIT, typename ET, typename OT>
__global__ __launch_bounds__(128, PASSES == 1 ? 2 : 1)
void bgemm(const ET* __restrict__ Ah, const ET* __restrict__ Al,
           const ET* __restrict__ Bh, const ET* __restrict__ Bl,
           const float* __restrict__ bias, const float* __restrict__ res,
           OT* __restrict__ C, bf16* __restrict__ Cl, float* __restrict__ psum,
           int N, int lda, int ldb, int kLen, float scale)
{
    constexpr bool FP8 = (sizeof(ET) == 1);
    constexpr int KCH = FP8 ? 128 : 64;          // K elements per 128B row
    constexpr int ESTEP = FP8 ? 16 : 8;          // elements per 16B chunk
    constexpr uint32_t OFF_B  = 16384;
    constexpr uint32_t OFF_BL = 32768;
    constexpr uint32_t OFF_AL = 49152;
    constexpr uint32_t STG = (PASSES == 3) ? 65536u : 32768u;

    extern __shared__ char smem[];
    const uint32_t sb = smem_u32(smem);
    const int tid = threadIdx.x;
    const int lane = tid & 31;
    const int wid = tid >> 5;
    const int warp_m = wid >> 1;
    const int warp_n = wid & 1;
    const int row0 = blockIdx.y * 128;
    const int col0 = blockIdx.x * 128;
    const int kOff = blockIdx.z * kLen;
    if (blockIdx.z) C += (size_t)blockIdx.z * NROWS * N;

    float d[4][8][4];
#pragma unroll
    for (int i = 0; i < 4; i++)
#pragma unroll
        for (int j = 0; j < 8; j++)
#pragma unroll
            for (int q = 0; q < 4; q++) d[i][j][q] = 0.0f;

    const int niter = kLen / KCH;

    auto issue = [&](int j) {
        const uint32_t sbase = sb + (uint32_t)(j % NST) * STG;
        const int k0 = kOff + j * KCH;
#pragma unroll
        for (int l = 0; l < 8; ++l) {
            int c = tid + l * 128;           // 0..1023
            int r = c >> 3, c16 = c & 7;
            uint32_t soff = SWZ((uint32_t)(r * 128 + c16 * 16));
            size_t ga = (size_t)(row0 + r) * lda + k0 + c16 * ESTEP;
            size_t gb = (size_t)(col0 + r) * ldb + k0 + c16 * ESTEP;
            cpa16(sbase + soff, Ah + ga);
            cpa16(sbase + OFF_B + soff, Bh + gb);
            if constexpr (PASSES == 3) {
                cpa16(sbase + OFF_BL + soff, Bl + gb);
                cpa16(sbase + OFF_AL + soff, Al + ga);
            }
        }
        cpa_commit();
    };

    const int lmat = lane >> 3;
    const int lrow = lane & 7;
    const int aRowB = warp_m * 64 + ((lmat & 1) << 3) + lrow;
    const int bRowB = warp_n * 64 + ((lmat & 1) << 3) + lrow;
    const int kHalf = (lmat >> 1) << 4;

    auto compute = [&](int stage) {
        const uint32_t aB = sb + (uint32_t)stage * STG;
        const uint32_t bB = aB + OFF_B;
#pragma unroll
        for (int ks = 0; ks < 4; ++ks) {
            int kb = ks * 32 + kHalf;        // byte offset in 128B row
            uint32_t af[4][4], bf2[4][4];
#pragma unroll
            for (int mi = 0; mi < 4; ++mi)
                ldsm4(af[mi], aB + SWZ((uint32_t)((aRowB + mi * 16) * 128 + kb)));
#pragma unroll
            for (int nj = 0; nj < 4; ++nj)
                ldsm4(bf2[nj], bB + SWZ((uint32_t)((bRowB + nj * 16) * 128 + kb)));
#pragma unroll
            for (int mi = 0; mi < 4; ++mi)
#pragma unroll
                for (int nj = 0; nj < 4; ++nj)
#pragma unroll
                    for (int s = 0; s < 2; ++s) {
                        if constexpr (FP8)
                            mma32f8(d[mi][nj * 2 + s], af[mi], bf2[nj][s], bf2[nj][s + 2]);
                        else
                            mma16(d[mi][nj * 2 + s], af[mi], bf2[nj][s], bf2[nj][s + 2]);
                    }
            if constexpr (PASSES == 3) {
                uint32_t al[4][4], bl[4][4];
#pragma unroll
                for (int nj = 0; nj < 4; ++nj)
                    ldsm4(bl[nj], aB + OFF_BL + SWZ((uint32_t)((bRowB + nj * 16) * 128 + kb)));
#pragma unroll
                for (int mi = 0; mi < 4; ++mi)
                    ldsm4(al[mi], aB + OFF_AL + SWZ((uint32_t)((aRowB + mi * 16) * 128 + kb)));
#pragma unroll
                for (int mi = 0; mi < 4; ++mi)
#pragma unroll
                    for (int nj = 0; nj < 4; ++nj)
#pragma unroll
                        for (int s = 0; s < 2; ++s) {
                            mma16(d[mi][nj * 2 + s], af[mi], bl[nj][s], bl[nj][s + 2]);
                            mma16(d[mi][nj * 2 + s], al[mi], bf2[nj][s], bf2[nj][s + 2]);
                        }
            }
        }
    };

    // ---- two-sync pipelined mainloop (proven) ----
#pragma unroll
    for (int s = 0; s < NST - 1; ++s)
        if (s < niter) issue(s);

    for (int it = 0; it < niter; ++it) {
        if (it + NST - 1 < niter) issue(it + NST - 1);
        int allow = min(niter, it + NST) - it - 1;
        if (allow >= 2)      cpa_wait<2>();
        else if (allow == 1) cpa_wait<1>();
        else                 cpa_wait<0>();
        __syncthreads();
        compute(it % NST);
        __syncthreads();
    }

    // ---- epilogue ----
    const int g4 = lane >> 2, t4 = lane & 3;
    float rsum[4][2];
    if (EPI == EPI_EXP) {
#pragma unroll
        for (int mi = 0; mi < 4; ++mi) { rsum[mi][0] = 0.0f; rsum[mi][1] = 0.0f; }
    }
#pragma unroll
    for (int mi = 0; mi < 4; ++mi) {
#pragma unroll
        for (int hf = 0; hf < 2; ++hf) {
            int row = row0 + warp_m * 64 + mi * 16 + g4 + hf * 8;
#pragma unroll
            for (int nt = 0; nt < 8; ++nt) {
                int col = col0 + warp_n * 64 + nt * 8 + t4 * 2;
                size_t gi = (size_t)row * N + col;
                float vx = d[mi][nt][hf * 2 + 0];
                float vy = d[mi][nt][hf * 2 + 1];
                if (EPI == EPI_NONE) {
                    vx *= scale; vy *= scale;
                } else if (EPI == EPI_EXP) {
                    vx = exp_fast(vx * scale); vy = exp_fast(vy * scale);
                    rsum[mi][hf] += vx + vy;
                } else if (EPI == EPI_BG) {
                    float2 bv = *(const float2*)(bias + col);
                    vx = gelu_exact(vx + bv.x); vy = gelu_exact(vy + bv.y);
                } else { // EPI_BGR
                    float2 bv = *(const float2*)(bias + col);
                    float2 rv = *(const float2*)(res + gi);
                    vx = rv.x + gelu_exact(vx + bv.x);
                    vy = rv.y + gelu_exact(vy + bv.y);
                }
                if constexpr (OSPLIT) {
                    float hx, lx, hy, ly;
                    splitbf(vx, hx, lx); splitbf(vy, hy, ly);
                    *(uint32_t*)((bf16*)C + gi) = packbf(hx, hy);
                    *(uint32_t*)(Cl + gi) = packbf(lx, ly);
                } else if constexpr (sizeof(OT) == 1) {
                    // e4m3 output with 1/16 scale (cancelled via invS*16 downstream)
                    *(uint16_t*)((uint8_t*)C + gi) = packf8(vx * 0.0625f, vy * 0.0625f);
                } else if constexpr (sizeof(OT) == 4) {
                    *(float2*)((float*)C + gi) = make_float2(vx, vy);
                } else {
                    *(uint32_t*)((bf16*)C + gi) = packbf(vx, vy);
                }
            }
        }
    }

    if (EPI == EPI_EXP) {
#pragma unroll
        for (int mi = 0; mi < 4; ++mi)
#pragma unroll
            for (int hf = 0; hf < 2; ++hf) {
                float v = rsum[mi][hf];
                v += __shfl_xor_sync(0xffffffffu, v, 1);
                v += __shfl_xor_sync(0xffffffffu, v, 2);
                rsum[mi][hf] = v;
            }
        float* psmem = (float*)smem;
        if (t4 == 0) {
#pragma unroll
            for (int mi = 0; mi < 4; ++mi)
#pragma unroll
                for (int hf = 0; hf < 2; ++hf) {
                    int rloc = warp_m * 64 + mi * 16 + hf * 8 + g4;
                    psmem[rloc * 2 + warp_n] = rsum[mi][hf];
                }
        }
        __syncthreads();
        psum[(size_t)blockIdx.x * NROWS + row0 + tid] = psmem[tid * 2] + psmem[tid * 2 + 1];
    }
}

// ---------------- combine row partials -> inverse (warp per row) ----------------
__global__ void rowsum_combine_kernel(const float* __restrict__ psum, float* __restrict__ inv, int ntiles)
{
    int w = (blockIdx.x * blockDim.x + threadIdx.x) >> 5;
    int lane = threadIdx.x & 31;
    if (w >= NROWS) return;
    float s = 0.0f;
    for (int x = lane; x < ntiles; x += 32) s += psum[(size_t)x * NROWS + w];
#pragma unroll
    for (int o = 16; o > 0; o >>= 1) s += __shfl_xor_sync(0xffffffffu, s, o);
    if (lane == 0) inv[w] = 1.0f / s;
}

// ---------------- fused preprocessing (one launch) ----------------
struct PrepEnt { const float* s; void* dh; bf16* dl; int R, C, trans, fp8, tiles; };
struct PrepArgs { PrepEnt e[9]; };

__global__ void prep_kernel(PrepArgs a)
{
    __shared__ float tile[32][33];
    int b = blockIdx.x;
    int i = 0;
    while (b >= a.e[i].tiles) { b -= a.e[i].tiles; ++i; }
    const PrepEnt E = a.e[i];
    const int ctiles = E.C / 32;
    const int r0 = (b / ctiles) * 32;
    const int c0 = (b % ctiles) * 32;
    const int x = threadIdx.x;

    if (!E.trans) {
#pragma unroll
        for (int yy = threadIdx.y; yy < 32; yy += 8) {
            size_t idx = (size_t)(r0 + yy) * E.C + c0 + x;
            float v = E.s[idx];
            if (E.dl) {
                float h, l; splitbf(v, h, l);
                ((bf16*)E.dh)[idx] = __float2bfloat16(h);
                E.dl[idx] = __float2bfloat16(l);
            } else {
                ((bf16*)E.dh)[idx] = __float2bfloat16(v);
            }
        }
    } else {
#pragma unroll
        for (int yy = threadIdx.y; yy < 32; yy += 8)
            tile[yy][x] = E.s[(size_t)(r0 + yy) * E.C + c0 + x];
        __syncthreads();
#pragma unroll
        for (int yy = threadIdx.y; yy < 32; yy += 8) {
            float v = tile[x][yy];
            size_t o = (size_t)(c0 + yy) * E.R + r0 + x;
            if (E.fp8) {
                ((__nv_fp8_e4m3*)E.dh)[o] = __nv_fp8_e4m3(v);
            } else if (E.dl) {
                float h, l; splitbf(v, h, l);
                ((bf16*)E.dh)[o] = __float2bfloat16(h);
                E.dl[o] = __float2bfloat16(l);
            } else {
                ((bf16*)E.dh)[o] = __float2bfloat16(v);
            }
        }
    }
}

__global__ void transpose_h_kernel(const float* __restrict__ src, bf16* __restrict__ dh, int R, int Cc)
{
    __shared__ float tile[32][33];
    const int r0 = blockIdx.x * 32;
    const int c0 = blockIdx.y * 32;
    const int x = threadIdx.x;
#pragma unroll
    for (int yy = threadIdx.y; yy < 32; yy += 8)
        tile[yy][x] = src[(size_t)(r0 + yy) * Cc + c0 + x];
    __syncthreads();
#pragma unroll
    for (int yy = threadIdx.y; yy < 32; yy += 8)
        dh[(size_t)(c0 + yy) * R + r0 + x] = __float2bfloat16(tile[x][yy]);
}

// ---------------- split-K reductions ----------------
__global__ void reduce_blend_kernel(const float* __restrict__ part, const float* __restrict__ X,
                                    const float* __restrict__ invS, const float* __restrict__ alpha,
                                    float* __restrict__ X2, bf16* __restrict__ X2h,
                                    int nsp, float postscale)
{
    size_t i = (size_t)blockIdx.x * 256 + threadIdx.x;
    const float4* p = (const float4*)part;
    const size_t stride = (size_t)NROWS * DDIM / 4;
    float4 s = p[i];
    for (int z = 1; z < nsp; ++z) {
        float4 t = p[i + (size_t)z * stride];
        s.x += t.x; s.y += t.y; s.z += t.z; s.w += t.w;
    }
    int row = (int)((i * 4) / DDIM);
    float rs = invS[row] * postscale;
    float blend = 1.0f / (1.0f + exp_fast(-alpha[0]));
    float4 xv = ((const float4*)X)[i];
    float4 o;
    o.x = blend * (s.x * rs) + (1.0f - blend) * xv.x;
    o.y = blend * (s.y * rs) + (1.0f - blend) * xv.y;
    o.z = blend * (s.z * rs) + (1.0f - blend) * xv.z;
    o.w = blend * (s.w * rs) + (1.0f - blend) * xv.w;
    ((float4*)X2)[i] = o;
    ((uint2*)X2h)[i] = make_uint2(packbf(o.x, o.y), packbf(o.z, o.w));
}

__global__ void reduce_rs_kernel(const float* __restrict__ part, const float* __restrict__ invA,
                                 bf16* __restrict__ Th, int nsp)
{
    size_t i = (size_t)blockIdx.x * 256 + threadIdx.x;
    const float4* p = (const float4*)part;
    const size_t stride = (size_t)NROWS * DDIM / 4;
    float4 s = p[i];
    for (int z = 1; z < nsp; ++z) {
        float4 t = p[i + (size_t)z * stride];
        s.x += t.x; s.y += t.y; s.z += t.z; s.w += t.w;
    }
    int row = (int)((i * 4) / DDIM);
    float rs = invA[row];
    ((uint2*)Th)[i] = make_uint2(packbf(s.x * rs, s.y * rs), packbf(s.z * rs, s.w * rs));
}

// ---------------- final head ----------------
__global__ void head_kernel(const float* __restrict__ h2, const float* __restrict__ W3,
                            const float* __restrict__ b3, float* __restrict__ out)
{
    const int row = blockIdx.x;
    const int t = threadIdx.x;
    const float* hr = h2 + (size_t)row * H2DIM;

    float a0 = 0.f, a1 = 0.f, a2 = 0.f, a3 = 0.f;
    for (int k = t; k < H2DIM; k += 64) {
        const float hv = hr[k];
        a0 = fmaf(hv, W3[k * 4 + 0], a0);
        a1 = fmaf(hv, W3[k * 4 + 1], a1);
        a2 = fmaf(hv, W3[k * 4 + 2], a2);
        a3 = fmaf(hv, W3[k * 4 + 3], a3);
    }
    __shared__ float s0[64], s1[64], s2[64], s3[64];
    s0[t] = a0; s1[t] = a1; s2[t] = a2; s3[t] = a3;
    __syncthreads();
    for (int off = 32; off > 0; off >>= 1) {
        if (t < off) {
            s0[t] += s0[t + off]; s1[t] += s1[t + off];
            s2[t] += s2[t + off]; s3[t] += s3[t + off];
        }
        __syncthreads();
    }
    if (t == 0) {
        const float r0 = s0[0] + b3[0];
        const float r1 = s1[0] + b3[1];
        const float r2 = s2[0] + b3[2];
        const float r3 = s3[0] + b3[3];
        out[0 * NROWS + row] = r0;
        out[1 * NROWS + row] = softplus_stable(r1) + 1e-6f;
        out[2 * NROWS + row] = fminf(softplus_stable(r2), 28.0f) + 1.01f;
        out[3 * NROWS + row] = softplus_stable(r3) + 1e-6f;
    }
}

// ---------------- host side ----------------
template<typename T>
static T* sym(const void* s) {
    void* p = nullptr;
    cudaGetSymbolAddress(&p, (const void*)s);
    return (T*)p;
}

template<int PASSES, int EPI, bool OSPLIT, typename ET, typename OT>
static void launch_gemm(const ET* Ah, const ET* Al, const ET* Bh, const ET* Bl,
                        const float* bias, const float* res, OT* C, bf16* Cl, float* psum,
                        int N, int lda, int ldb, int Ktot, int splits, float scale)
{
    int smemB = NST * ((PASSES == 3) ? 65536 : 32768);
    cudaFuncSetAttribute(bgemm<PASSES, EPI, OSPLIT, ET, OT>,
                         cudaFuncAttributeMaxDynamicSharedMemorySize, smemB);
    dim3 grid(N / 128, NROWS / 128, splits);
    bgemm<PASSES, EPI, OSPLIT, ET, OT><<<grid, 128, smemB>>>(
        Ah, Al, Bh, Bl, bias, res, C, Cl, psum, N, lda, ldb, Ktot / splits, scale);
}

extern "C" void kernel_launch(void* const* d_in, const int* in_sizes, int n_in,
                              void* d_out, int out_size)
{
    const float* X      = (const float*)d_in[0];
    const float* ctx_k  = (const float*)d_in[1];
    const float* ctx_v  = (const float*)d_in[2];
    const float* Wq_hop = (const float*)d_in[3];
    const float* alpha  = (const float*)d_in[4];
    const float* Wq_mol = (const float*)d_in[5];
    const float* Wk_mol = (const float*)d_in[6];
    const float* Wg     = (const float*)d_in[7];
    const float* bg     = (const float*)d_in[8];
    const float* W1     = (const float*)d_in[9];
    const float* b1     = (const float*)d_in[10];
    const float* W2     = (const float*)d_in[11];
    const float* b2     = (const float*)d_in[12];
    const float* W3     = (const float*)d_in[13];
    const float* b3     = (const float*)d_in[14];
    float* out = (float*)d_out;

    uint8_t *S = sym<uint8_t>(g_S), *Vt8 = sym<uint8_t>(g_Vt8);
    bf16 *Kc = sym<bf16>(g_Kc);
    bf16 *Xh = sym<bf16>(g_Xh), *Xl = sym<bf16>(g_Xl), *Qb = sym<bf16>(g_Qb);
    bf16 *X2h = sym<bf16>(g_X2h), *X2th = sym<bf16>(g_X2th);
    bf16 *QKm = sym<bf16>(g_QKm);
    bf16 *A2h = sym<bf16>(g_A2h), *Th = sym<bf16>(g_Th);
    bf16 *Hh = sym<bf16>(g_Hh), *Hl = sym<bf16>(g_Hl);
    bf16 *H1h = sym<bf16>(g_H1h), *H1l = sym<bf16>(g_H1l);
    bf16 *Wqh_h = sym<bf16>(g_Wqh_h), *Wqh_l = sym<bf16>(g_Wqh_l);
    bf16 *Wqkm = sym<bf16>(g_Wqkm);
    bf16 *Wg_h = sym<bf16>(g_Wg_h);
    bf16 *W1_h = sym<bf16>(g_W1_h), *W1_l = sym<bf16>(g_W1_l);
    bf16 *W2_h = sym<bf16>(g_W2_h), *W2_l = sym<bf16>(g_W2_l);
    float *X2 = sym<float>(g_X2), *H2 = sym<float>(g_H2);
    float *invS = sym<float>(g_invS), *invA = sym<float>(g_invA);
    float *part = sym<float>(g_part), *psum = sym<float>(g_psum);

    const float inv_sqrt_dinner = 0.0625f;              // 1/sqrt(256)
    const float inv_sqrt_d = 0.036084391824351615f;     // 1/sqrt(768)

    // ---- fused preprocessing ----
    {
        PrepArgs pa;
        auto ent = [](const float* s, void* dh, bf16* dl, int R, int C, int tr, int f8) {
            PrepEnt e; e.s = s; e.dh = dh; e.dl = dl; e.R = R; e.C = C; e.trans = tr;
            e.fp8 = f8; e.tiles = (R / 32) * (C / 32); return e;
        };
        pa.e[0] = ent(X,      Xh,    Xl,      NROWS, DDIM,   0, 0);
        pa.e[1] = ent(ctx_k,  Kc,    nullptr, MCTX,  DINNER, 0, 0);
        pa.e[2] = ent(ctx_v,  Vt8,   nullptr, MCTX,  DDIM,   1, 1);   // e4m3 transpose
        pa.e[3] = ent(Wq_hop, Wqh_h, Wqh_l,   DDIM,  DINNER, 1, 0);
        pa.e[4] = ent(Wq_mol, Wqkm,                 nullptr, DDIM, DDIM, 1, 0);
        pa.e[5] = ent(Wk_mol, Wqkm + (size_t)768 * DDIM, nullptr, DDIM, DDIM, 1, 0);
        pa.e[6] = ent(Wg,     Wg_h,  nullptr, DDIM,  DDIM,   1, 0);
        pa.e[7] = ent(W1,     W1_h,  W1_l,    DDIM,  H1DIM,  1, 0);
        pa.e[8] = ent(W2,     W2_h,  W2_l,    H1DIM, H2DIM,  1, 0);
        int total = 0;
        for (int i = 0; i < 9; ++i) total += pa.e[i].tiles;
        prep_kernel<<<total, dim3(32, 8)>>>(pa);
    }

    // 1. Q = X @ Wq_hop -> bf16                 (N=256, K=768)   split-3
    launch_gemm<3, EPI_NONE, false>(Xh, Xl, Wqh_h, Wqh_l, (const float*)nullptr, (const float*)nullptr,
                                    Qb, (bf16*)nullptr, (float*)nullptr, DINNER, DDIM, DDIM, DDIM, 1, 1.0f);

    // 2. S = e4m3(exp(Q @ ctx_k^T / 16) / 16) + fp32 row partials  (N=32768, K=256)
    launch_gemm<1, EPI_EXP, false>(Qb, (const bf16*)nullptr, Kc, (const bf16*)nullptr,
                                   (const float*)nullptr, (const float*)nullptr,
                                   S, (bf16*)nullptr, psum, MCTX, DINNER, DINNER, DINNER, 1, inv_sqrt_dinner);

    // 3. invS = 1 / sum of 256 tile partials
    rowsum_combine_kernel<<<NROWS * 32 / 256, 256>>>(psum, invS, MCTX / 128);

    // 4. enriched partials = S_fp8 @ Vt_fp8^T (FP8 mma, split-K=8);
    //    X2 = blend*(16*invS*sum) + (1-blend)*X  (16 cancels the e4m3 storage scale)
    launch_gemm<1, EPI_NONE, false>(S, (const uint8_t*)nullptr, Vt8, (const uint8_t*)nullptr,
                                    (const float*)nullptr, (const float*)nullptr,
                                    part, (bf16*)nullptr, (float*)nullptr, DDIM, MCTX, MCTX, MCTX, 8, 1.0f);
    reduce_blend_kernel<<<NROWS * DDIM / 1024, 256>>>(part, X, invS, alpha, X2, X2h, 8, 16.0f);
    transpose_h_kernel<<<dim3(NROWS / 32, DDIM / 32), dim3(32, 8)>>>(X2, X2th, NROWS, DDIM);

    // 5. [Qm|Km] = X2 @ [Wq_mol|Wk_mol]  (N=1536, K=768)  single bf16
    launch_gemm<1, EPI_NONE, false>(X2h, (const bf16*)nullptr, Wqkm, (const bf16*)nullptr,
                                    (const float*)nullptr, (const float*)nullptr,
                                    QKm, (bf16*)nullptr, (float*)nullptr, 1536, DDIM, DDIM, DDIM, 1, 1.0f);

    // 6. A2 = exp(Qm @ Km^T / sqrt(768)) -> bf16 + row partials (N=4096, K=768)
    launch_gemm<1, EPI_EXP, false>(QKm, (const bf16*)nullptr, QKm + 768, (const bf16*)nullptr,
                                   (const float*)nullptr, (const float*)nullptr,
                                   A2h, (bf16*)nullptr, psum, NROWS, 1536, 1536, DDIM, 1, inv_sqrt_d);

    // 7. invA = 1 / sum of 32 tile partials
    rowsum_combine_kernel<<<NROWS * 32 / 256, 256>>>(psum, invA, NROWS / 128);

    // 8. T partials = A2 @ X2 (split-K=4); T = invA*sum -> bf16
    launch_gemm<1, EPI_NONE, false>(A2h, (const bf16*)nullptr, X2th, (const bf16*)nullptr,
                                    (const float*)nullptr, (const float*)nullptr,
                                    part, (bf16*)nullptr, (float*)nullptr, DDIM, NROWS, NROWS, NROWS, 4, 1.0f);
    reduce_rs_kernel<<<NROWS * DDIM / 1024, 256>>>(part, invA, Th, 4);

    // 9. H = X2 + gelu(T @ Wg + bg)  (N=768, K=768)  single; split hi/lo output
    launch_gemm<1, EPI_BGR, true>(Th, (const bf16*)nullptr, Wg_h, (const bf16*)nullptr, bg, X2,
                                  Hh, Hl, (float*)nullptr, DDIM, DDIM, DDIM, DDIM, 1, 1.0f);

    // 10. H1 = gelu(H @ W1 + b1)  (N=512, K=768)  split-3
    launch_gemm<3, EPI_BG, true>(Hh, Hl, W1_h, W1_l, b1, (const float*)nullptr,
                                 H1h, H1l, (float*)nullptr, H1DIM, DDIM, DDIM, DDIM, 1, 1.0f);

    // 11. H2 = gelu(H1 @ W2 + b2) -> fp32  (N=256, K=512)  split-3
    launch_gemm<3, EPI_BG, false>(H1h, H1l, W2_h, W2_l, b2, (const float*)nullptr,
                                  H2, (bf16*)nullptr, (float*)nullptr, H2DIM, H1DIM, H1DIM, H1DIM, 1, 1.0f);

    // 12. head -> out (mu | v | a | b)
    head_kernel<<<NROWS, 64>>>(H2, W3, b3, out);

    (void)in_sizes; (void)n_in; (void)out_size;
}

// round 17
// speedup vs baseline: 1.0752x; 1.0752x over previous
#include <cuda_runtime.h>
#include <cuda_bf16.h>
#include <math.h>
#include <stdint.h>

// ---------------- problem constants ----------------
#define NROWS 4096
#define DDIM  768
#define DINNER 256
#define MCTX  32768
#define H1DIM 512
#define H2DIM 256

typedef __nv_bfloat16 bf16;

// ---------------- scratch (device globals; no allocation allowed) ----------------
__device__ bf16 g_S[(size_t)NROWS * MCTX];
__device__ bf16 g_Vt[(size_t)DDIM * MCTX];
__device__ bf16 g_Kc[(size_t)MCTX * DINNER];
__device__ bf16 g_Xh[(size_t)NROWS * DDIM];
__device__ bf16 g_Xl[(size_t)NROWS * DDIM];
__device__ bf16 g_Qb[(size_t)NROWS * DINNER];
__device__ bf16 g_X2h[(size_t)NROWS * DDIM];
__device__ bf16 g_X2th[(size_t)DDIM * NROWS];
__device__ bf16 g_QKm[(size_t)NROWS * 1536];      // Qm | Km concat
__device__ bf16 g_A2h[(size_t)NROWS * NROWS];
__device__ bf16 g_Th[(size_t)NROWS * DDIM];
__device__ bf16 g_Hh[(size_t)NROWS * DDIM];
__device__ bf16 g_Hl[(size_t)NROWS * DDIM];
__device__ bf16 g_H1h[(size_t)NROWS * H1DIM];
__device__ bf16 g_H1l[(size_t)NROWS * H1DIM];
// pre-transposed weights
__device__ bf16 g_Wqh_h[(size_t)DINNER * DDIM];
__device__ bf16 g_Wqh_l[(size_t)DINNER * DDIM];
__device__ bf16 g_Wqkm[(size_t)1536 * DDIM];      // Wq_mol^T | Wk_mol^T
__device__ bf16 g_Wg_h[(size_t)DDIM * DDIM];
__device__ bf16 g_W1_h[(size_t)H1DIM * DDIM];
__device__ bf16 g_W1_l[(size_t)H1DIM * DDIM];
__device__ bf16 g_W2_h[(size_t)H2DIM * H1DIM];
__device__ bf16 g_W2_l[(size_t)H2DIM * H1DIM];
// fp32
__device__ float g_X2[(size_t)NROWS * DDIM];
__device__ float g_H2[(size_t)NROWS * H2DIM];
__device__ float g_invS[NROWS];
__device__ float g_invA[NROWS];
__device__ float g_part[(size_t)8 * NROWS * DDIM];
__device__ float g_psum[(size_t)512 * NROWS];

// ---------------- helpers ----------------
__device__ __forceinline__ uint32_t smem_u32(const void* p) {
    uint32_t a;
    asm("{ .reg .u64 t; cvta.to.shared.u64 t, %1; cvt.u32.u64 %0, t; }" : "=r"(a) : "l"(p));
    return a;
}
#define SWZ(off) ((off) ^ (((off) >> 3) & 0x70))

__device__ __forceinline__ uint32_t packbf(float x0, float x1) {
    uint32_t r;
    asm("cvt.rn.bf16x2.f32 %0, %1, %2;" : "=r"(r) : "f"(x1), "f"(x0));
    return r;
}
__device__ __forceinline__ void splitbf(float x, float& h, float& l) {
    h = __bfloat162float(__float2bfloat16(x));
    l = x - h;
}
__device__ __forceinline__ float gelu_exact(float x) {
    return 0.5f * x * (1.0f + erff(x * 0.70710678118654752f));
}
__device__ __forceinline__ float softplus_stable(float x) {
    return (x > 20.0f) ? x : log1pf(expf(x));
}

__device__ __forceinline__ void cpa16(uint32_t dst, const void* src) {
    asm volatile("cp.async.cg.shared.global [%0], [%1], 16;" :: "r"(dst), "l"(src));
}
__device__ __forceinline__ void cpa_commit() {
    asm volatile("cp.async.commit_group;" ::: "memory");
}
template<int N>
__device__ __forceinline__ void cpa_wait() {
    asm volatile("cp.async.wait_group %0;" :: "n"(N) : "memory");
}

__device__ __forceinline__ void ldsm4(uint32_t* r, uint32_t addr) {
    asm volatile("ldmatrix.sync.aligned.m8n8.x4.shared.b16 {%0,%1,%2,%3}, [%4];"
        : "=r"(r[0]), "=r"(r[1]), "=r"(r[2]), "=r"(r[3]) : "r"(addr));
}
__device__ __forceinline__ void mma16(float* d, const uint32_t* a, uint32_t b0, uint32_t b1) {
    asm volatile("mma.sync.aligned.m16n8k16.row.col.f32.bf16.bf16.f32 "
        "{%0,%1,%2,%3}, {%4,%5,%6,%7}, {%8,%9}, {%0,%1,%2,%3};"
        : "+f"(d[0]), "+f"(d[1]), "+f"(d[2]), "+f"(d[3])
        : "r"(a[0]), "r"(a[1]), "r"(a[2]), "r"(a[3]), "r"(b0), "r"(b1));
}

// ---------------- unified bf16 GEMM ----------------
// C[4096,N] = epi(A @ B^T), K-major bf16, strides lda/ldb. 128x128x64 tiles,
// 4 warps (2m x 2n), warp 64x64. PROVEN two-sync 3-stage cp.async pipeline.
#define EPI_NONE 0
#define EPI_EXP 1
#define EPI_BG 2
#define EPI_BGR 3

#define NST 3

template<int PASSES, int EPI, bool OSPLIT, typename OT>
__global__ __launch_bounds__(128, PASSES == 1 ? 2 : 1)
void bgemm(const bf16* __restrict__ Ah, const bf16* __restrict__ Al,
           const bf16* __restrict__ Bh, const bf16* __restrict__ Bl,
           const float* __restrict__ bias, const float* __restrict__ res,
           OT* __restrict__ C, bf16* __restrict__ Cl, float* __restrict__ psum,
           int N, int lda, int ldb, int kLen, float scale)
{
    constexpr uint32_t OFF_B  = 16384;
    constexpr uint32_t OFF_BL = 32768;
    constexpr uint32_t OFF_AL = 49152;
    constexpr uint32_t STG = (PASSES == 3) ? 65536u : 32768u;

    extern __shared__ char smem[];
    const uint32_t sb = smem_u32(smem);
    const int tid = threadIdx.x;
    const int lane = tid & 31;
    const int wid = tid >> 5;
    const int warp_m = wid >> 1;
    const int warp_n = wid & 1;
    const int row0 = blockIdx.y * 128;
    const int col0 = blockIdx.x * 128;
    const int kOff = blockIdx.z * kLen;
    if (blockIdx.z) C += (size_t)blockIdx.z * NROWS * N;

    float d[4][8][4];
#pragma unroll
    for (int i = 0; i < 4; i++)
#pragma unroll
        for (int j = 0; j < 8; j++)
#pragma unroll
            for (int q = 0; q < 4; q++) d[i][j][q] = 0.0f;

    const int niter = kLen >> 6;

    auto issue = [&](int j) {
        const uint32_t sbase = sb + (uint32_t)(j % NST) * STG;
        const int k0 = kOff + j * 64;
#pragma unroll
        for (int l = 0; l < 8; ++l) {
            int c = tid + l * 128;           // 0..1023
            int r = c >> 3, c16 = c & 7;
            uint32_t soff = SWZ((uint32_t)(r * 128 + c16 * 16));
            size_t ga = (size_t)(row0 + r) * lda + k0 + c16 * 8;
            size_t gb = (size_t)(col0 + r) * ldb + k0 + c16 * 8;
            cpa16(sbase + soff, Ah + ga);
            cpa16(sbase + OFF_B + soff, Bh + gb);
            if constexpr (PASSES == 3) {
                cpa16(sbase + OFF_BL + soff, Bl + gb);
                cpa16(sbase + OFF_AL + soff, Al + ga);
            }
        }
        cpa_commit();
    };

    const int lmat = lane >> 3;
    const int lrow = lane & 7;
    const int aRowB = warp_m * 64 + ((lmat & 1) << 3) + lrow;
    const int bRowB = warp_n * 64 + ((lmat & 1) << 3) + lrow;
    const int kHalf = (lmat >> 1) << 4;

    auto compute = [&](int stage) {
        const uint32_t aB = sb + (uint32_t)stage * STG;
        const uint32_t bB = aB + OFF_B;
#pragma unroll
        for (int ks = 0; ks < 4; ++ks) {
            int kb = ks * 32 + kHalf;
            uint32_t af[4][4], bf2[4][4];
#pragma unroll
            for (int mi = 0; mi < 4; ++mi)
                ldsm4(af[mi], aB + SWZ((uint32_t)((aRowB + mi * 16) * 128 + kb)));
#pragma unroll
            for (int nj = 0; nj < 4; ++nj)
                ldsm4(bf2[nj], bB + SWZ((uint32_t)((bRowB + nj * 16) * 128 + kb)));
#pragma unroll
            for (int mi = 0; mi < 4; ++mi)
#pragma unroll
                for (int nj = 0; nj < 4; ++nj)
#pragma unroll
                    for (int s = 0; s < 2; ++s)
                        mma16(d[mi][nj * 2 + s], af[mi], bf2[nj][s], bf2[nj][s + 2]);
            if constexpr (PASSES == 3) {
                uint32_t al[4][4], bl[4][4];
#pragma unroll
                for (int nj = 0; nj < 4; ++nj)
                    ldsm4(bl[nj], aB + OFF_BL + SWZ((uint32_t)((bRowB + nj * 16) * 128 + kb)));
#pragma unroll
                for (int mi = 0; mi < 4; ++mi)
                    ldsm4(al[mi], aB + OFF_AL + SWZ((uint32_t)((aRowB + mi * 16) * 128 + kb)));
#pragma unroll
                for (int mi = 0; mi < 4; ++mi)
#pragma unroll
                    for (int nj = 0; nj < 4; ++nj)
#pragma unroll
                        for (int s = 0; s < 2; ++s) {
                            mma16(d[mi][nj * 2 + s], af[mi], bl[nj][s], bl[nj][s + 2]);
                            mma16(d[mi][nj * 2 + s], al[mi], bf2[nj][s], bf2[nj][s + 2]);
                        }
            }
        }
    };

    // ---- two-sync pipelined mainloop (proven; do not reorder) ----
#pragma unroll
    for (int s = 0; s < NST - 1; ++s)
        if (s < niter) issue(s);

    for (int it = 0; it < niter; ++it) {
        if (it + NST - 1 < niter) issue(it + NST - 1);
        int allow = min(niter, it + NST) - it - 1;
        if (allow >= 2)      cpa_wait<2>();
        else if (allow == 1) cpa_wait<1>();
        else                 cpa_wait<0>();
        __syncthreads();
        compute(it % NST);
        __syncthreads();
    }

    // ---- epilogue (expf: MUFU overlaps; exp_fast regressed via reg pressure) ----
    const int g4 = lane >> 2, t4 = lane & 3;
    float rsum[4][2];
    if (EPI == EPI_EXP) {
#pragma unroll
        for (int mi = 0; mi < 4; ++mi) { rsum[mi][0] = 0.0f; rsum[mi][1] = 0.0f; }
    }
#pragma unroll
    for (int mi = 0; mi < 4; ++mi) {
#pragma unroll
        for (int hf = 0; hf < 2; ++hf) {
            int row = row0 + warp_m * 64 + mi * 16 + g4 + hf * 8;
#pragma unroll
            for (int nt = 0; nt < 8; ++nt) {
                int col = col0 + warp_n * 64 + nt * 8 + t4 * 2;
                size_t gi = (size_t)row * N + col;
                float vx = d[mi][nt][hf * 2 + 0];
                float vy = d[mi][nt][hf * 2 + 1];
                if (EPI == EPI_NONE) {
                    vx *= scale; vy *= scale;
                } else if (EPI == EPI_EXP) {
                    vx = expf(vx * scale); vy = expf(vy * scale);
                    rsum[mi][hf] += vx + vy;
                } else if (EPI == EPI_BG) {
                    float2 bv = *(const float2*)(bias + col);
                    vx = gelu_exact(vx + bv.x); vy = gelu_exact(vy + bv.y);
                } else { // EPI_BGR
                    float2 bv = *(const float2*)(bias + col);
                    float2 rv = *(const float2*)(res + gi);
                    vx = rv.x + gelu_exact(vx + bv.x);
                    vy = rv.y + gelu_exact(vy + bv.y);
                }
                if constexpr (OSPLIT) {
                    float hx, lx, hy, ly;
                    splitbf(vx, hx, lx); splitbf(vy, hy, ly);
                    *(uint32_t*)((bf16*)C + gi) = packbf(hx, hy);
                    *(uint32_t*)(Cl + gi) = packbf(lx, ly);
                } else if constexpr (sizeof(OT) == 4) {
                    *(float2*)((float*)C + gi) = make_float2(vx, vy);
                } else {
                    *(uint32_t*)((bf16*)C + gi) = packbf(vx, vy);
                }
            }
        }
    }

    if (EPI == EPI_EXP) {
#pragma unroll
        for (int mi = 0; mi < 4; ++mi)
#pragma unroll
            for (int hf = 0; hf < 2; ++hf) {
                float v = rsum[mi][hf];
                v += __shfl_xor_sync(0xffffffffu, v, 1);
                v += __shfl_xor_sync(0xffffffffu, v, 2);
                rsum[mi][hf] = v;
            }
        float* psmem = (float*)smem;   // stages dead (mainloop ended with a sync)
        if (t4 == 0) {
#pragma unroll
            for (int mi = 0; mi < 4; ++mi)
#pragma unroll
                for (int hf = 0; hf < 2; ++hf) {
                    int rloc = warp_m * 64 + mi * 16 + hf * 8 + g4;
                    psmem[rloc * 2 + warp_n] = rsum[mi][hf];
                }
        }
        __syncthreads();
        psum[(size_t)blockIdx.x * NROWS + row0 + tid] = psmem[tid * 2] + psmem[tid * 2 + 1];
    }
}

// ---------------- combine row partials -> inverse (warp per row) ----------------
__global__ void rowsum_combine_kernel(const float* __restrict__ psum, float* __restrict__ inv, int ntiles)
{
    int w = (blockIdx.x * blockDim.x + threadIdx.x) >> 5;
    int lane = threadIdx.x & 31;
    if (w >= NROWS) return;
    float s = 0.0f;
    for (int x = lane; x < ntiles; x += 32) s += psum[(size_t)x * NROWS + w];
#pragma unroll
    for (int o = 16; o > 0; o >>= 1) s += __shfl_xor_sync(0xffffffffu, s, o);
    if (lane == 0) inv[w] = 1.0f / s;
}

// ---------------- fused preprocessing (one launch) ----------------
struct PrepEnt { const float* s; bf16* dh; bf16* dl; int R, C, trans, tiles; };
struct PrepArgs { PrepEnt e[9]; };

__global__ void prep_kernel(PrepArgs a)
{
    __shared__ float tile[32][33];
    int b = blockIdx.x;
    int i = 0;
    while (b >= a.e[i].tiles) { b -= a.e[i].tiles; ++i; }
    const PrepEnt E = a.e[i];
    const int ctiles = E.C / 32;
    const int r0 = (b / ctiles) * 32;
    const int c0 = (b % ctiles) * 32;
    const int x = threadIdx.x;

    if (!E.trans) {
#pragma unroll
        for (int yy = threadIdx.y; yy < 32; yy += 8) {
            size_t idx = (size_t)(r0 + yy) * E.C + c0 + x;
            float v = E.s[idx];
            if (E.dl) {
                float h, l; splitbf(v, h, l);
                E.dh[idx] = __float2bfloat16(h);
                E.dl[idx] = __float2bfloat16(l);
            } else {
                E.dh[idx] = __float2bfloat16(v);
            }
        }
    } else {
#pragma unroll
        for (int yy = threadIdx.y; yy < 32; yy += 8)
            tile[yy][x] = E.s[(size_t)(r0 + yy) * E.C + c0 + x];
        __syncthreads();
#pragma unroll
        for (int yy = threadIdx.y; yy < 32; yy += 8) {
            float v = tile[x][yy];
            size_t o = (size_t)(c0 + yy) * E.R + r0 + x;
            if (E.dl) {
                float h, l; splitbf(v, h, l);
                E.dh[o] = __float2bfloat16(h);
                E.dl[o] = __float2bfloat16(l);
            } else {
                E.dh[o] = __float2bfloat16(v);
            }
        }
    }
}

// bf16 -> bf16 transpose (X2h -> X2th); half the read traffic of the fp32 version
__global__ void transpose_bb_kernel(const bf16* __restrict__ src, bf16* __restrict__ dh, int R, int Cc)
{
    __shared__ bf16 tile[32][33];
    const int r0 = blockIdx.x * 32;
    const int c0 = blockIdx.y * 32;
    const int x = threadIdx.x;
#pragma unroll
    for (int yy = threadIdx.y; yy < 32; yy += 8)
        tile[yy][x] = src[(size_t)(r0 + yy) * Cc + c0 + x];
    __syncthreads();
#pragma unroll
    for (int yy = threadIdx.y; yy < 32; yy += 8)
        dh[(size_t)(c0 + yy) * R + r0 + x] = tile[x][yy];
}

// ---------------- split-K reductions ----------------
__global__ void reduce_blend_kernel(const float* __restrict__ part, const float* __restrict__ X,
                                    const float* __restrict__ invS, const float* __restrict__ alpha,
                                    float* __restrict__ X2, bf16* __restrict__ X2h, int nsp)
{
    size_t i = (size_t)blockIdx.x * 256 + threadIdx.x;
    const float4* p = (const float4*)part;
    const size_t stride = (size_t)NROWS * DDIM / 4;
    float4 s = p[i];
    for (int z = 1; z < nsp; ++z) {
        float4 t = p[i + (size_t)z * stride];
        s.x += t.x; s.y += t.y; s.z += t.z; s.w += t.w;
    }
    int row = (int)((i * 4) / DDIM);
    float rs = invS[row];
    float blend = 1.0f / (1.0f + expf(-alpha[0]));
    float4 xv = ((const float4*)X)[i];
    float4 o;
    o.x = blend * (s.x * rs) + (1.0f - blend) * xv.x;
    o.y = blend * (s.y * rs) + (1.0f - blend) * xv.y;
    o.z = blend * (s.z * rs) + (1.0f - blend) * xv.z;
    o.w = blend * (s.w * rs) + (1.0f - blend) * xv.w;
    ((float4*)X2)[i] = o;
    ((uint2*)X2h)[i] = make_uint2(packbf(o.x, o.y), packbf(o.z, o.w));
}

__global__ void reduce_rs_kernel(const float* __restrict__ part, const float* __restrict__ invA,
                                 bf16* __restrict__ Th, int nsp)
{
    size_t i = (size_t)blockIdx.x * 256 + threadIdx.x;
    const float4* p = (const float4*)part;
    const size_t stride = (size_t)NROWS * DDIM / 4;
    float4 s = p[i];
    for (int z = 1; z < nsp; ++z) {
        float4 t = p[i + (size_t)z * stride];
        s.x += t.x; s.y += t.y; s.z += t.z; s.w += t.w;
    }
    int row = (int)((i * 4) / DDIM);
    float rs = invA[row];
    ((uint2*)Th)[i] = make_uint2(packbf(s.x * rs, s.y * rs), packbf(s.z * rs, s.w * rs));
}

// ---------------- final head ----------------
__global__ void head_kernel(const float* __restrict__ h2, const float* __restrict__ W3,
                            const float* __restrict__ b3, float* __restrict__ out)
{
    const int row = blockIdx.x;
    const int t = threadIdx.x;
    const float* hr = h2 + (size_t)row * H2DIM;

    float a0 = 0.f, a1 = 0.f, a2 = 0.f, a3 = 0.f;
    for (int k = t; k < H2DIM; k += 64) {
        const float hv = hr[k];
        a0 = fmaf(hv, W3[k * 4 + 0], a0);
        a1 = fmaf(hv, W3[k * 4 + 1], a1);
        a2 = fmaf(hv, W3[k * 4 + 2], a2);
        a3 = fmaf(hv, W3[k * 4 + 3], a3);
    }
    __shared__ float s0[64], s1[64], s2[64], s3[64];
    s0[t] = a0; s1[t] = a1; s2[t] = a2; s3[t] = a3;
    __syncthreads();
    for (int off = 32; off > 0; off >>= 1) {
        if (t < off) {
            s0[t] += s0[t + off]; s1[t] += s1[t + off];
            s2[t] += s2[t + off]; s3[t] += s3[t + off];
        }
        __syncthreads();
    }
    if (t == 0) {
        const float r0 = s0[0] + b3[0];
        const float r1 = s1[0] + b3[1];
        const float r2 = s2[0] + b3[2];
        const float r3 = s3[0] + b3[3];
        out[0 * NROWS + row] = r0;
        out[1 * NROWS + row] = softplus_stable(r1) + 1e-6f;
        out[2 * NROWS + row] = fminf(softplus_stable(r2), 28.0f) + 1.01f;
        out[3 * NROWS + row] = softplus_stable(r3) + 1e-6f;
    }
}

// ---------------- host side ----------------
template<typename T>
static T* sym(const void* s) {
    void* p = nullptr;
    cudaGetSymbolAddress(&p, (const void*)s);
    return (T*)p;
}

template<int PASSES, int EPI, bool OSPLIT, typename OT>
static void launch_gemm(const bf16* Ah, const bf16* Al, const bf16* Bh, const bf16* Bl,
                        const float* bias, const float* res, OT* C, bf16* Cl, float* psum,
                        int N, int lda, int ldb, int Ktot, int splits, float scale)
{
    int smemB = NST * ((PASSES == 3) ? 65536 : 32768);
    cudaFuncSetAttribute(bgemm<PASSES, EPI, OSPLIT, OT>,
                         cudaFuncAttributeMaxDynamicSharedMemorySize, smemB);
    dim3 grid(N / 128, NROWS / 128, splits);
    bgemm<PASSES, EPI, OSPLIT, OT><<<grid, 128, smemB>>>(
        Ah, Al, Bh, Bl, bias, res, C, Cl, psum, N, lda, ldb, Ktot / splits, scale);
}

extern "C" void kernel_launch(void* const* d_in, const int* in_sizes, int n_in,
                              void* d_out, int out_size)
{
    const float* X      = (const float*)d_in[0];
    const float* ctx_k  = (const float*)d_in[1];
    const float* ctx_v  = (const float*)d_in[2];
    const float* Wq_hop = (const float*)d_in[3];
    const float* alpha  = (const float*)d_in[4];
    const float* Wq_mol = (const float*)d_in[5];
    const float* Wk_mol = (const float*)d_in[6];
    const float* Wg     = (const float*)d_in[7];
    const float* bg     = (const float*)d_in[8];
    const float* W1     = (const float*)d_in[9];
    const float* b1     = (const float*)d_in[10];
    const float* W2     = (const float*)d_in[11];
    const float* b2     = (const float*)d_in[12];
    const float* W3     = (const float*)d_in[13];
    const float* b3     = (const float*)d_in[14];
    float* out = (float*)d_out;

    bf16 *S = sym<bf16>(g_S), *Vt = sym<bf16>(g_Vt), *Kc = sym<bf16>(g_Kc);
    bf16 *Xh = sym<bf16>(g_Xh), *Xl = sym<bf16>(g_Xl), *Qb = sym<bf16>(g_Qb);
    bf16 *X2h = sym<bf16>(g_X2h), *X2th = sym<bf16>(g_X2th);
    bf16 *QKm = sym<bf16>(g_QKm);
    bf16 *A2h = sym<bf16>(g_A2h), *Th = sym<bf16>(g_Th);
    bf16 *Hh = sym<bf16>(g_Hh), *Hl = sym<bf16>(g_Hl);
    bf16 *H1h = sym<bf16>(g_H1h), *H1l = sym<bf16>(g_H1l);
    bf16 *Wqh_h = sym<bf16>(g_Wqh_h), *Wqh_l = sym<bf16>(g_Wqh_l);
    bf16 *Wqkm = sym<bf16>(g_Wqkm);
    bf16 *Wg_h = sym<bf16>(g_Wg_h);
    bf16 *W1_h = sym<bf16>(g_W1_h), *W1_l = sym<bf16>(g_W1_l);
    bf16 *W2_h = sym<bf16>(g_W2_h), *W2_l = sym<bf16>(g_W2_l);
    float *X2 = sym<float>(g_X2), *H2 = sym<float>(g_H2);
    float *invS = sym<float>(g_invS), *invA = sym<float>(g_invA);
    float *part = sym<float>(g_part), *psum = sym<float>(g_psum);

    const float inv_sqrt_dinner = 0.0625f;              // 1/sqrt(256)
    const float inv_sqrt_d = 0.036084391824351615f;     // 1/sqrt(768)

    // ---- fused preprocessing: one launch for all conversions/transposes ----
    {
        PrepArgs pa;
        auto ent = [](const float* s, bf16* dh, bf16* dl, int R, int C, int tr) {
            PrepEnt e; e.s = s; e.dh = dh; e.dl = dl; e.R = R; e.C = C; e.trans = tr;
            e.tiles = (R / 32) * (C / 32); return e;
        };
        pa.e[0] = ent(X,      Xh,    Xl,      NROWS, DDIM,   0);
        pa.e[1] = ent(ctx_k,  Kc,    nullptr, MCTX,  DINNER, 0);
        pa.e[2] = ent(ctx_v,  Vt,    nullptr, MCTX,  DDIM,   1);
        pa.e[3] = ent(Wq_hop, Wqh_h, Wqh_l,   DDIM,  DINNER, 1);
        pa.e[4] = ent(Wq_mol, Wqkm,                 nullptr, DDIM, DDIM, 1);
        pa.e[5] = ent(Wk_mol, Wqkm + (size_t)768 * DDIM, nullptr, DDIM, DDIM, 1);
        pa.e[6] = ent(Wg,     Wg_h,  nullptr, DDIM,  DDIM,   1);
        pa.e[7] = ent(W1,     W1_h,  W1_l,    DDIM,  H1DIM,  1);
        pa.e[8] = ent(W2,     W2_h,  W2_l,    H1DIM, H2DIM,  1);
        int total = 0;
        for (int i = 0; i < 9; ++i) total += pa.e[i].tiles;
        prep_kernel<<<total, dim3(32, 8)>>>(pa);
    }

    // 1. Q = X @ Wq_hop -> bf16                 (N=256, K=768)   split-3
    launch_gemm<3, EPI_NONE, false>(Xh, Xl, Wqh_h, Wqh_l, nullptr, nullptr,
                                    Qb, nullptr, nullptr, DINNER, DDIM, DDIM, DDIM, 1, 1.0f);

    // 2. S = exp(Q @ ctx_k^T / 16) -> bf16 + fused row partials  (N=32768, K=256)
    launch_gemm<1, EPI_EXP, false>(Qb, nullptr, Kc, nullptr, nullptr, nullptr,
                                   S, nullptr, psum, MCTX, DINNER, DINNER, DINNER, 1, inv_sqrt_dinner);

    // 3. invS = 1 / sum of 256 tile partials (warp per row)
    rowsum_combine_kernel<<<NROWS * 32 / 256, 256>>>(psum, invS, MCTX / 128);

    // 4. enriched partials = S @ Vt^T (split-K=8); X2 = blend*(invS*sum) + (1-blend)*X
    launch_gemm<1, EPI_NONE, false>(S, nullptr, Vt, nullptr, nullptr, nullptr,
                                    part, nullptr, nullptr, DDIM, MCTX, MCTX, MCTX, 8, 1.0f);
    reduce_blend_kernel<<<NROWS * DDIM / 1024, 256>>>(part, X, invS, alpha, X2, X2h, 8);
    transpose_bb_kernel<<<dim3(NROWS / 32, DDIM / 32), dim3(32, 8)>>>(X2h, X2th, NROWS, DDIM);

    // 5. [Qm|Km] = X2 @ [Wq_mol|Wk_mol]  (N=1536, K=768)  single, one launch
    launch_gemm<1, EPI_NONE, false>(X2h, nullptr, Wqkm, nullptr, nullptr, nullptr,
                                    QKm, nullptr, nullptr, 1536, DDIM, DDIM, DDIM, 1, 1.0f);

    // 6. A2 = exp(Qm @ Km^T / sqrt(768)) -> bf16 + row partials (N=4096, K=768)
    launch_gemm<1, EPI_EXP, false>(QKm, nullptr, QKm + 768, nullptr, nullptr, nullptr,
                                   A2h, nullptr, psum, NROWS, 1536, 1536, DDIM, 1, inv_sqrt_d);

    // 7. invA = 1 / sum of 32 tile partials
    rowsum_combine_kernel<<<NROWS * 32 / 256, 256>>>(psum, invA, NROWS / 128);

    // 8. T partials = A2 @ X2 (split-K=4); T = invA*sum -> bf16
    launch_gemm<1, EPI_NONE, false>(A2h, nullptr, X2th, nullptr, nullptr, nullptr,
                                    part, nullptr, nullptr, DDIM, NROWS, NROWS, NROWS, 4, 1.0f);
    reduce_rs_kernel<<<NROWS * DDIM / 1024, 256>>>(part, invA, Th, 4);

    // 9. H = X2 + gelu(T @ Wg + bg)  (N=768, K=768)  single; split hi/lo output
    launch_gemm<1, EPI_BGR, true>(Th, nullptr, Wg_h, nullptr, bg, X2,
                                  Hh, Hl, nullptr, DDIM, DDIM, DDIM, DDIM, 1, 1.0f);

    // 10. H1 = gelu(H @ W1 + b1)  (N=512, K=768)  split-3
    launch_gemm<3, EPI_BG, true>(Hh, Hl, W1_h, W1_l, b1, nullptr,
                                 H1h, H1l, nullptr, H1DIM, DDIM, DDIM, DDIM, 1, 1.0f);

    // 11. H2 = gelu(H1 @ W2 + b2) -> fp32  (N=256, K=512)  split-3
    launch_gemm<3, EPI_BG, false>(H1h, H1l, W2_h, W2_l, b2, nullptr,
                                  H2, nullptr, nullptr, H2DIM, H1DIM, H1DIM, H1DIM, 1, 1.0f);

    // 12. head -> out (mu | v | a | b)
    head_kernel<<<NROWS, 64>>>(H2, W3, b3, out);

    (void)in_sizes; (void)n_in; (void)out_size;
}